// round 12
// baseline (speedup 1.0000x reference)
#include <cuda_runtime.h>
#include <cuda_fp16.h>
#include <math.h>
#include <stdint.h>

#define BATCH 8
#define CDIM 192
#define C3 576
#define HEADS 8
#define CHH 24
#define NPIX 16384
#define IMW 128

// ---------------- scratch (device globals; allocation-free rule) ------------
__device__ float g_qkv1[BATCH * C3 * NPIX];
__device__ float g_qkv2[BATCH * C3 * NPIX];    // only v region used now
__device__ float g_gram[BATCH * HEADS * CHH * CHH];
__device__ float g_nq[BATCH * CDIM];
__device__ float g_nk[BATCH * CDIM];
__device__ __half g_wq[C3 * CDIM];
__device__ __half g_weff[BATCH * CDIM * CDIM];

#define MMA_F16(d, a, bb) \
    asm volatile("mma.sync.aligned.m16n8k16.row.col.f32.f16.f16.f32 " \
        "{%0,%1,%2,%3}, {%4,%5,%6,%7}, {%8,%9}, {%0,%1,%2,%3};" \
        : "+f"((d)[0]), "+f"((d)[1]), "+f"((d)[2]), "+f"((d)[3]) \
        : "r"((a)[0]), "r"((a)[1]), "r"((a)[2]), "r"((a)[3]), \
          "r"((bb)[0]), "r"((bb)[1]))

#define LDSM_X4(r0, r1, r2, r3, addr) \
    asm volatile("ldmatrix.sync.aligned.m8n8.x4.shared.b16 {%0,%1,%2,%3}, [%4];" \
        : "=r"(r0), "=r"(r1), "=r"(r2), "=r"(r3) : "r"(addr))

__device__ __forceinline__ uint32_t pack_h2(__half a, __half b) {
    return ((uint32_t)__half_as_ushort(b) << 16) | __half_as_ushort(a);
}
__device__ __forceinline__ uint32_t smem_u32(const void* p) {
    uint32_t a;
    asm("{ .reg .u64 t; cvta.to.shared.u64 t, %1; cvt.u32.u64 %0, t; }"
        : "=r"(a) : "l"(p));
    return a;
}
__device__ __forceinline__ void cp_async16(uint32_t dst, const void* src) {
    asm volatile("cp.async.cg.shared.global [%0], [%1], 16;" :: "r"(dst), "l"(src));
}

// ---------------------------------------------------------------------------
// HMMA GEMM, B-panel-stationary (unchanged round-11 winner).
// ---------------------------------------------------------------------------
#define LDAE 200
#define LDBF 200
#define A_BYTES (192 * LDAE * 2)
#define SMEM_GEMM (A_BYTES + 64 * LDBF * 2)   // 102400 bytes

__global__ __launch_bounds__(256, 2)
void gemm_mma(const __half* __restrict__ W, long long wstride,
              const float* __restrict__ X, long long xstride,
              float* __restrict__ Y, long long ystride, int NO)
{
    extern __shared__ __half smem[];
    __half* Ah = smem;
    __half* Bs = smem + 192 * LDAE;

    const int b = blockIdx.y;
    const int n0 = blockIdx.x * 64;
    const __half* Wp = W + (long long)b * wstride;
    const float* Xp = X + (long long)b * xstride;
    float* Yp = Y + (long long)b * ystride;

    const int tid = threadIdx.x;
    const int lane = tid & 31;
    const int wid = tid >> 5;
    const int wm = wid & 3;
    const int wn = wid >> 2;

    const uint32_t a_base = smem_u32(Ah);
    const uint32_t b_base = smem_u32(Bs);

    {
#pragma unroll
        for (int c = 0; c < 18; ++c) {
            int ch = c * 256 + tid;
            int row = ch / 24, col = ch % 24;
            uint32_t doff = (uint32_t)(row * LDAE + col * 8) * 2u;
            cp_async16(a_base + doff, Wp + (long long)row * CDIM + col * 8);
        }
        asm volatile("cp.async.commit_group;");
    }
#pragma unroll
    for (int it = 0; it < 6; ++it) {
        int id = it * 256 + tid;
        int kr = (id >> 4) * 2;
        int nc = (id & 15) * 4;
        float4 r0 = *reinterpret_cast<const float4*>(&Xp[(long long)kr * NPIX + n0 + nc]);
        float4 r1 = *reinterpret_cast<const float4*>(&Xp[(long long)(kr + 1) * NPIX + n0 + nc]);
        float e0[4] = {r0.x, r0.y, r0.z, r0.w};
        float e1[4] = {r1.x, r1.y, r1.z, r1.w};
#pragma unroll
        for (int i = 0; i < 4; ++i)
            *reinterpret_cast<uint32_t*>(&Bs[(nc + i) * LDBF + kr]) =
                pack_h2(__float2half(e0[i]), __float2half(e1[i]));
    }

    const int lg = lane >> 3, lr = lane & 7;
    uint32_t a_row[3];
#pragma unroll
    for (int mi = 0; mi < 3; ++mi) {
        int row = wm * 48 + mi * 16 + (lg & 1) * 8 + lr;
        a_row[mi] = a_base + (uint32_t)(row * LDAE + (lg >> 1) * 8) * 2u;
    }
    uint32_t b_row[2];
#pragma unroll
    for (int nj = 0; nj < 2; ++nj) {
        int n = wn * 32 + (nj * 2 + (lg >> 1)) * 8 + lr;
        b_row[nj] = b_base + (uint32_t)(n * LDBF + (lg & 1) * 8) * 2u;
    }

    for (int op = 0; op < NO; ++op) {
        asm volatile("cp.async.wait_group 0;");
        __syncthreads();

        float acc[3][4][4];
#pragma unroll
        for (int mi = 0; mi < 3; ++mi)
#pragma unroll
            for (int ni = 0; ni < 4; ++ni)
#pragma unroll
                for (int q = 0; q < 4; ++q) acc[mi][ni][q] = 0.f;

#pragma unroll
        for (int ks = 0; ks < 12; ++ks) {
            const uint32_t koff = (uint32_t)(ks * 16) * 2u;
            uint32_t fa[3][4], fb[4][2];
#pragma unroll
            for (int mi = 0; mi < 3; ++mi)
                LDSM_X4(fa[mi][0], fa[mi][1], fa[mi][2], fa[mi][3],
                        a_row[mi] + koff);
#pragma unroll
            for (int nj = 0; nj < 2; ++nj)
                LDSM_X4(fb[2 * nj][0], fb[2 * nj][1], fb[2 * nj + 1][0], fb[2 * nj + 1][1],
                        b_row[nj] + koff);
#pragma unroll
            for (int mi = 0; mi < 3; ++mi)
#pragma unroll
                for (int ni = 0; ni < 4; ++ni)
                    MMA_F16(acc[mi][ni], fa[mi], fb[ni]);
        }

        __syncthreads();

        if (op + 1 < NO) {
            const __half* Wn = Wp + (long long)(op + 1) * 192 * CDIM;
#pragma unroll
            for (int c = 0; c < 18; ++c) {
                int ch = c * 256 + tid;
                int row = ch / 24, col = ch % 24;
                uint32_t doff = (uint32_t)(row * LDAE + col * 8) * 2u;
                cp_async16(a_base + doff, Wn + (long long)row * CDIM + col * 8);
            }
            asm volatile("cp.async.commit_group;");
        }

        const int ob = op * 192;
#pragma unroll
        for (int mi = 0; mi < 3; ++mi) {
            int r = ob + wm * 48 + mi * 16 + (lane >> 2);
#pragma unroll
            for (int ni = 0; ni < 4; ++ni) {
                int c = n0 + wn * 32 + ni * 8 + (lane & 3) * 2;
                *reinterpret_cast<float2*>(&Yp[(long long)r * NPIX + c]) =
                    make_float2(acc[mi][ni][0], acc[mi][ni][1]);
                *reinterpret_cast<float2*>(&Yp[(long long)(r + 8) * NPIX + c]) =
                    make_float2(acc[mi][ni][2], acc[mi][ni][3]);
            }
        }
    }
}

// ---------------------------------------------------------------------------
// Weight prep (also zeroes gram/norm accumulators when base==0)
// ---------------------------------------------------------------------------
__global__ void prep_wqkv_kernel(const float* __restrict__ W, int base)
{
    int lin = blockIdx.x * blockDim.x + threadIdx.x;
    if (base == 0) {
        if (lin < BATCH * HEADS * CHH * CHH) g_gram[lin] = 0.f;
        if (lin < BATCH * CDIM) { g_nq[lin] = 0.f; g_nk[lin] = 0.f; }
    }
    int idx = base + lin;
    if (idx >= C3 * CDIM) return;
    g_wq[idx] = __float2half(W[idx]);
}

// ---------------------------------------------------------------------------
// Fused dwconv(q,k) + feature-mul + Gram + norms.
// Block: (y-strip of 8 rows, b*8+head). 256 threads. SMEM: 3-row ring of the
// 48 q/k channels, QF/KF[24][128] conv-output tiles, feat row, dw weights.
// ---------------------------------------------------------------------------
#define RING_SZ (3 * 48 * 128)
#define DG_QF   RING_SZ
#define DG_KF   (DG_QF + 24 * 128)
#define DG_FT   (DG_KF + 24 * 128)
#define DG_DW   (DG_FT + 24 * 128)
#define DG_SMEM ((DG_DW + 48 * 9) * 4)     // 112320 bytes

__global__ __launch_bounds__(256, 1)
void dwgram_kernel(const float* __restrict__ feat,
                   const float* __restrict__ wdw)
{
    extern __shared__ float sm[];
    float* RING = sm;
    float* QF = sm + DG_QF;
    float* KF = sm + DG_KF;
    float* FT = sm + DG_FT;
    float* DW = sm + DG_DW;

    const int bh = blockIdx.y;
    const int b = bh >> 3, hd = bh & 7;
    const int y0 = blockIdx.x * 8;
    const int tid = threadIdx.x;

    const long long qoff = ((long long)b * C3 + hd * CHH) * NPIX;       // q chans
    const long long koff = ((long long)b * C3 + CDIM + hd * CHH) * NPIX; // k chans
    const long long foff = ((long long)b * CDIM + hd * CHH) * NPIX;

    // ---- stage dw weights for our 48 channels ----
    for (int i = tid; i < 48 * 9; i += 256) {
        int ch = i / 9, w = i % 9;
        int gch = (ch < CHH) ? hd * CHH + ch : CDIM + hd * CHH + (ch - CHH);
        DW[i] = wdw[gch * 9 + w];
    }

    // ---- prologue: load rows y0-1 and y0 into ring ----
#pragma unroll
    for (int pr = 0; pr < 2; ++pr) {
        int yy = y0 - 1 + pr;
        int slot = ((yy % 3) + 3) % 3;
        float* dst = RING + slot * 48 * 128;
        bool inb = (yy >= 0);
#pragma unroll
        for (int j = 0; j < 6; ++j) {
            int id = j * 256 + tid;
            int ch = id >> 5, xq = (id & 31) * 4;
            float4 v = make_float4(0.f, 0.f, 0.f, 0.f);
            if (inb) {
                long long base = (ch < CHH) ? qoff + (long long)ch * NPIX
                                            : koff + (long long)(ch - CHH) * NPIX;
                v = *reinterpret_cast<const float4*>(&g_qkv1[base + yy * IMW + xq]);
            }
            *reinterpret_cast<float4*>(&dst[ch * 128 + xq]) = v;
        }
    }

    // gram accumulators
    const int g = tid >> 6, l = tid & 63;
    const int i0 = (l >> 3) * 3, j0 = (l & 7) * 3;
    float acc[3][3];
#pragma unroll
    for (int a = 0; a < 3; ++a)
#pragma unroll
        for (int c = 0; c < 3; ++c) acc[a][c] = 0.f;
    float nqp = 0.f, nkp = 0.f;

    for (int y = y0; y < y0 + 8; ++y) {
        // (1) load ring row y+1 and feat row y
        {
            int yy = y + 1;
            float* dst = RING + (yy % 3) * 48 * 128;
            bool inb = (yy <= IMW - 1);
#pragma unroll
            for (int j = 0; j < 6; ++j) {
                int id = j * 256 + tid;
                int ch = id >> 5, xq = (id & 31) * 4;
                float4 v = make_float4(0.f, 0.f, 0.f, 0.f);
                if (inb) {
                    long long base = (ch < CHH) ? qoff + (long long)ch * NPIX
                                                : koff + (long long)(ch - CHH) * NPIX;
                    v = *reinterpret_cast<const float4*>(&g_qkv1[base + yy * IMW + xq]);
                }
                *reinterpret_cast<float4*>(&dst[ch * 128 + xq]) = v;
            }
#pragma unroll
            for (int j = 0; j < 3; ++j) {
                int id = j * 256 + tid;
                int c = id >> 5, xq = (id & 31) * 4;
                *reinterpret_cast<float4*>(&FT[c * 128 + xq]) =
                    *reinterpret_cast<const float4*>(&feat[foff + (long long)c * NPIX + y * IMW + xq]);
            }
        }
        __syncthreads();   // S1: ring(y+1), FT visible

        // (2) conv row y -> QF/KF (x feat)
        {
            const float* r0 = RING + (((y - 1) % 3 + 3) % 3) * 48 * 128;
            const float* r1 = RING + (y % 3) * 48 * 128;
            const float* r2 = RING + ((y + 1) % 3) * 48 * 128;
            const float* rows[3] = {r0, r1, r2};
            const int xq = (tid & 31) * 4;
            const int ch0 = tid >> 5;
#pragma unroll
            for (int j = 0; j < 6; ++j) {
                int ch = ch0 + j * 8;
                const float* w = DW + ch * 9;
                float o0 = 0.f, o1 = 0.f, o2 = 0.f, o3 = 0.f;
#pragma unroll
                for (int r = 0; r < 3; ++r) {
                    const float* rr = rows[r] + ch * 128;
                    float4 c = *reinterpret_cast<const float4*>(&rr[xq]);
                    float lft = (xq > 0) ? rr[xq - 1] : 0.f;
                    float rgt = (xq < 124) ? rr[xq + 4] : 0.f;
                    float w0 = w[r * 3], w1 = w[r * 3 + 1], w2 = w[r * 3 + 2];
                    o0 += w0 * lft + w1 * c.x + w2 * c.y;
                    o1 += w0 * c.x + w1 * c.y + w2 * c.z;
                    o2 += w0 * c.y + w1 * c.z + w2 * c.w;
                    o3 += w0 * c.z + w1 * c.w + w2 * rgt;
                }
                int fc = (ch < CHH) ? ch : ch - CHH;
                float4 f = *reinterpret_cast<const float4*>(&FT[fc * 128 + xq]);
                float4 res = make_float4(o0 * f.x, o1 * f.y, o2 * f.z, o3 * f.w);
                if (ch < CHH)
                    *reinterpret_cast<float4*>(&QF[ch * 128 + xq]) = res;
                else
                    *reinterpret_cast<float4*>(&KF[(ch - CHH) * 128 + xq]) = res;
            }
        }
        __syncthreads();   // S2: QF/KF ready

        // (3) gram + norms over this row's 128 pixels (group g: 32 px)
#pragma unroll 4
        for (int it = 0; it < 32; ++it) {
            int nn = g * 32 + ((it + l) & 31);
            float q0 = QF[(i0 + 0) * 128 + nn];
            float q1 = QF[(i0 + 1) * 128 + nn];
            float q2 = QF[(i0 + 2) * 128 + nn];
            float k0 = KF[(j0 + 0) * 128 + nn];
            float k1 = KF[(j0 + 1) * 128 + nn];
            float k2 = KF[(j0 + 2) * 128 + nn];
            acc[0][0] += q0 * k0; acc[0][1] += q0 * k1; acc[0][2] += q0 * k2;
            acc[1][0] += q1 * k0; acc[1][1] += q1 * k1; acc[1][2] += q1 * k2;
            acc[2][0] += q2 * k0; acc[2][1] += q2 * k1; acc[2][2] += q2 * k2;
        }
        if (l < CHH) {
#pragma unroll 4
            for (int it = 0; it < 32; ++it) {
                int nn = g * 32 + ((it + l) & 31);
                float qv = QF[l * 128 + nn]; nqp += qv * qv;
                float kv = KF[l * 128 + nn]; nkp += kv * kv;
            }
        }
        __syncthreads();   // S3: gram reads done before next ring/QF writes
    }

#pragma unroll
    for (int a = 0; a < 3; ++a)
#pragma unroll
        for (int c = 0; c < 3; ++c)
            atomicAdd(&g_gram[(bh * CHH + i0 + a) * CHH + j0 + c], acc[a][c]);
    if (l < CHH) {
        atomicAdd(&g_nq[b * CDIM + hd * CHH + l], nqp);
        atomicAdd(&g_nk[b * CDIM + hd * CHH + l], nkp);
    }
}

// ---------------------------------------------------------------------------
// 3x3 depthwise conv for V only (192 channels); 8 px/thread
// ---------------------------------------------------------------------------
__global__ void vconv_kernel(const float* __restrict__ in,
                             const float* __restrict__ wdw,
                             float* __restrict__ out)
{
    long long idx = (long long)blockIdx.x * blockDim.x + threadIdx.x;
    if (idx >= (long long)BATCH * CDIM * (NPIX / 8)) return;
    const int n8 = (int)(idx & (NPIX / 8 - 1));
    const int t = (int)(idx >> 11);
    const int cv = t % CDIM;
    const int b = t / CDIM;
    const long long gch = (long long)b * C3 + 2 * CDIM + cv;
    const int y = n8 >> 4;
    const int x0 = (n8 & 15) * 8;
    const float* w = wdw + (2 * CDIM + cv) * 9;
    const float* p = in + gch * NPIX;

    float o[8];
#pragma unroll
    for (int i = 0; i < 8; ++i) o[i] = 0.f;
#pragma unroll
    for (int r = 0; r < 3; ++r) {
        int yy = y + r - 1;
        if (yy < 0 || yy > IMW - 1) continue;
        const float* row = p + yy * IMW;
        float4 c0 = *reinterpret_cast<const float4*>(&row[x0]);
        float4 c1 = *reinterpret_cast<const float4*>(&row[x0 + 4]);
        float e[10];
        e[0] = (x0 > 0) ? row[x0 - 1] : 0.f;
        e[1] = c0.x; e[2] = c0.y; e[3] = c0.z; e[4] = c0.w;
        e[5] = c1.x; e[6] = c1.y; e[7] = c1.z; e[8] = c1.w;
        e[9] = (x0 < IMW - 8) ? row[x0 + 8] : 0.f;
        float w0 = w[r * 3], w1 = w[r * 3 + 1], w2 = w[r * 3 + 2];
#pragma unroll
        for (int i = 0; i < 8; ++i)
            o[i] += w0 * e[i] + w1 * e[i + 1] + w2 * e[i + 2];
    }
    float* op = out + gch * NPIX + y * IMW + x0;
    *reinterpret_cast<float4*>(op) = make_float4(o[0], o[1], o[2], o[3]);
    *reinterpret_cast<float4*>(op + 4) = make_float4(o[4], o[5], o[6], o[7]);
}

// ---------------------------------------------------------------------------
// Softmax + W_eff = W_proj @ A_blockdiag, emitted fp16 [192][192]
// ---------------------------------------------------------------------------
__global__ void softmax_weff_kernel(const float* __restrict__ temp,
                                    const float* __restrict__ Wp)
{
    const int b = blockIdx.x;
    const int t = threadIdx.x;            // 384
    __shared__ float A[HEADS][CHH][CHH];
    __shared__ float qinv[CDIM], kinv[CDIM];

    if (t < CDIM) {
        qinv[t] = 1.0f / fmaxf(sqrtf(g_nq[b * CDIM + t]), 1e-12f);
    } else if (t < 2 * CDIM) {
        int c = t - CDIM;
        kinv[c] = 1.0f / fmaxf(sqrtf(g_nk[b * CDIM + c]), 1e-12f);
    }
    __syncthreads();

    if (t < CDIM) {
        const int hd = t / CHH, i = t % CHH;
        const float tp = temp[hd];
        const float qi = qinv[hd * CHH + i];
        float row[CHH];
        float m = -1e30f;
#pragma unroll
        for (int j = 0; j < CHH; ++j) {
            float v = g_gram[((b * HEADS + hd) * CHH + i) * CHH + j]
                      * tp * qi * kinv[hd * CHH + j];
            row[j] = v;
            m = fmaxf(m, v);
        }
        float ssum = 0.f;
#pragma unroll
        for (int j = 0; j < CHH; ++j) { row[j] = expf(row[j] - m); ssum += row[j]; }
        float inv = 1.0f / ssum;
#pragma unroll
        for (int j = 0; j < CHH; ++j) A[hd][i][j] = row[j] * inv;
    }
    __syncthreads();

    for (int idx = t; idx < CDIM * CDIM; idx += 384) {
        const int o = idx / CDIM, cc = idx % CDIM;
        const int hd = cc / CHH, j = cc % CHH;
        float s = 0.f;
#pragma unroll
        for (int i = 0; i < CHH; ++i)
            s += Wp[o * CDIM + hd * CHH + i] * A[hd][i][j];
        g_weff[(long long)b * CDIM * CDIM + idx] = __float2half(s);
    }
}

// ---------------------------------------------------------------------------
extern "C" void kernel_launch(void* const* d_in, const int* in_sizes, int n_in,
                              void* d_out, int out_size)
{
    (void)in_sizes; (void)n_in; (void)out_size;
    const float* x     = (const float*)d_in[0];
    const float* feat  = (const float*)d_in[1];
    const float* Wqkv  = (const float*)d_in[2];
    const float* Wdw   = (const float*)d_in[3];
    const float* Wproj = (const float*)d_in[4];
    const float* temp  = (const float*)d_in[5];
    float* out = (float*)d_out;

    float *qkv1, *qkv2;
    __half *wq, *wf;
    cudaGetSymbolAddress((void**)&qkv1, g_qkv1);
    cudaGetSymbolAddress((void**)&qkv2, g_qkv2);
    cudaGetSymbolAddress((void**)&wq, g_wq);
    cudaGetSymbolAddress((void**)&wf, g_weff);

    static int smem_set = 0;
    if (!smem_set) {
        cudaFuncSetAttribute(gemm_mma, cudaFuncAttributeMaxDynamicSharedMemorySize,
                             SMEM_GEMM);
        cudaFuncSetAttribute(dwgram_kernel, cudaFuncAttributeMaxDynamicSharedMemorySize,
                             DG_SMEM);
        smem_set = 1;
    }

    const int HALF_W = C3 * CDIM / 2;

    // 1,2) weight prep (+ accumulator zeroing)
    prep_wqkv_kernel<<<(HALF_W + 255) / 256, 256>>>(Wqkv, 0);
    prep_wqkv_kernel<<<(HALF_W + 255) / 256, 256>>>(Wqkv, HALF_W);

    // 3) qkv1 = W_qkv @ x  (B-stationary, 3 o-panels per block)
    gemm_mma<<<dim3(NPIX / 64, BATCH), 256, SMEM_GEMM>>>(
        wq, 0LL, x, (long long)CDIM * NPIX, qkv1, (long long)C3 * NPIX, 3);

    // 4) fused dwconv(q,k) + gram + norms   (ncu slot 4)
    dwgram_kernel<<<dim3(16, BATCH * HEADS), 256, DG_SMEM>>>(feat, Wdw);

    // 5) depthwise conv for v only
    {
        long long total = (long long)BATCH * CDIM * (NPIX / 8);
        vconv_kernel<<<(int)((total + 255) / 256), 256>>>(qkv1, Wdw, qkv2);
    }

    // 6) softmax + W_eff (fp16)
    softmax_weff_kernel<<<BATCH, 384>>>(temp, Wproj);

    // 7) out = W_eff @ v
    gemm_mma<<<dim3(NPIX / 64, BATCH), 256, SMEM_GEMM>>>(
        wf, (long long)CDIM * CDIM,
        qkv2 + (long long)2 * CDIM * NPIX, (long long)C3 * NPIX,
        out, (long long)CDIM * NPIX, 1);
}

// round 13
// speedup vs baseline: 1.2560x; 1.2560x over previous
#include <cuda_runtime.h>
#include <cuda_fp16.h>
#include <math.h>
#include <stdint.h>

#define BATCH 8
#define CDIM 192
#define C3 576
#define HEADS 8
#define CHH 24
#define NPIX 16384
#define IMW 128

// ---------------- scratch (device globals; allocation-free rule) ------------
__device__ __half g_qkv1[BATCH * C3 * NPIX];     // 1x1-conv output, fp16
__device__ float g_qkv2[BATCH * 2 * CDIM * NPIX]; // dwconv q/k output, fp32
__device__ __half g_vh[BATCH * CDIM * NPIX];      // dwconv v output, fp16
__device__ float g_gram[BATCH * HEADS * CHH * CHH];
__device__ float g_nq[BATCH * CDIM];
__device__ float g_nk[BATCH * CDIM];
__device__ __half g_wq[C3 * CDIM];
__device__ __half g_weff[BATCH * CDIM * CDIM];

#define MMA_F16(d, a, bb) \
    asm volatile("mma.sync.aligned.m16n8k16.row.col.f32.f16.f16.f32 " \
        "{%0,%1,%2,%3}, {%4,%5,%6,%7}, {%8,%9}, {%0,%1,%2,%3};" \
        : "+f"((d)[0]), "+f"((d)[1]), "+f"((d)[2]), "+f"((d)[3]) \
        : "r"((a)[0]), "r"((a)[1]), "r"((a)[2]), "r"((a)[3]), \
          "r"((bb)[0]), "r"((bb)[1]))

#define LDSM_X4(r0, r1, r2, r3, addr) \
    asm volatile("ldmatrix.sync.aligned.m8n8.x4.shared.b16 {%0,%1,%2,%3}, [%4];" \
        : "=r"(r0), "=r"(r1), "=r"(r2), "=r"(r3) : "r"(addr))

__device__ __forceinline__ uint32_t pack_h2(__half a, __half b) {
    return ((uint32_t)__half_as_ushort(b) << 16) | __half_as_ushort(a);
}
__device__ __forceinline__ uint32_t smem_u32(const void* p) {
    uint32_t a;
    asm("{ .reg .u64 t; cvta.to.shared.u64 t, %1; cvt.u32.u64 %0, t; }"
        : "=r"(a) : "l"(p));
    return a;
}
__device__ __forceinline__ void cp_async16(uint32_t dst, const void* src) {
    asm volatile("cp.async.cg.shared.global [%0], [%1], 16;" :: "r"(dst), "l"(src));
}

// ---------------------------------------------------------------------------
// B staging + epilogue helpers (fp32 / fp16 variants)
// ---------------------------------------------------------------------------
#define LDAE 200
#define LDBF 200

__device__ __forceinline__ void stage_b(__half* Bs, const float* Xp, int n0, int id) {
    int kr = (id >> 4) * 2, nc = (id & 15) * 4;
    float4 r0 = *reinterpret_cast<const float4*>(&Xp[(long long)kr * NPIX + n0 + nc]);
    float4 r1 = *reinterpret_cast<const float4*>(&Xp[(long long)(kr + 1) * NPIX + n0 + nc]);
    float e0[4] = {r0.x, r0.y, r0.z, r0.w};
    float e1[4] = {r1.x, r1.y, r1.z, r1.w};
#pragma unroll
    for (int i = 0; i < 4; ++i)
        *reinterpret_cast<uint32_t*>(&Bs[(nc + i) * LDBF + kr]) =
            pack_h2(__float2half(e0[i]), __float2half(e1[i]));
}
__device__ __forceinline__ void stage_b(__half* Bs, const __half* Xp, int n0, int id) {
    int kr = (id >> 4) * 2, nc = (id & 15) * 4;
    uint2 r0 = *reinterpret_cast<const uint2*>(&Xp[(long long)kr * NPIX + n0 + nc]);
    uint2 r1 = *reinterpret_cast<const uint2*>(&Xp[(long long)(kr + 1) * NPIX + n0 + nc]);
    *reinterpret_cast<uint32_t*>(&Bs[(nc + 0) * LDBF + kr]) = __byte_perm(r0.x, r1.x, 0x5410);
    *reinterpret_cast<uint32_t*>(&Bs[(nc + 1) * LDBF + kr]) = __byte_perm(r0.x, r1.x, 0x7632);
    *reinterpret_cast<uint32_t*>(&Bs[(nc + 2) * LDBF + kr]) = __byte_perm(r0.y, r1.y, 0x5410);
    *reinterpret_cast<uint32_t*>(&Bs[(nc + 3) * LDBF + kr]) = __byte_perm(r0.y, r1.y, 0x7632);
}
__device__ __forceinline__ void st_out(float* p, float a, float b) {
    *reinterpret_cast<float2*>(p) = make_float2(a, b);
}
__device__ __forceinline__ void st_out(__half* p, float a, float b) {
    *reinterpret_cast<uint32_t*>(p) = pack_h2(__float2half(a), __float2half(b));
}

// ---------------------------------------------------------------------------
// HMMA GEMM, B-panel-stationary (round-11 winner), templated on B/out dtype.
// ---------------------------------------------------------------------------
#define A_BYTES (192 * LDAE * 2)
#define SMEM_GEMM (A_BYTES + 64 * LDBF * 2)   // 102400 bytes

template <typename TB, typename TO>
__global__ __launch_bounds__(256, 2)
void gemm_mma(const __half* __restrict__ W, long long wstride,
              const TB* __restrict__ X, long long xstride,
              TO* __restrict__ Y, long long ystride, int NO)
{
    extern __shared__ __half smem[];
    __half* Ah = smem;
    __half* Bs = smem + 192 * LDAE;

    const int b = blockIdx.y;
    const int n0 = blockIdx.x * 64;
    const __half* Wp = W + (long long)b * wstride;
    const TB* Xp = X + (long long)b * xstride;
    TO* Yp = Y + (long long)b * ystride;

    const int tid = threadIdx.x;
    const int lane = tid & 31;
    const int wid = tid >> 5;
    const int wm = wid & 3;
    const int wn = wid >> 2;

    const uint32_t a_base = smem_u32(Ah);
    const uint32_t b_base = smem_u32(Bs);

    {
#pragma unroll
        for (int c = 0; c < 18; ++c) {
            int ch = c * 256 + tid;
            int row = ch / 24, col = ch % 24;
            uint32_t doff = (uint32_t)(row * LDAE + col * 8) * 2u;
            cp_async16(a_base + doff, Wp + (long long)row * CDIM + col * 8);
        }
        asm volatile("cp.async.commit_group;");
    }
#pragma unroll
    for (int it = 0; it < 6; ++it)
        stage_b(Bs, Xp, n0, it * 256 + tid);

    const int lg = lane >> 3, lr = lane & 7;
    uint32_t a_row[3];
#pragma unroll
    for (int mi = 0; mi < 3; ++mi) {
        int row = wm * 48 + mi * 16 + (lg & 1) * 8 + lr;
        a_row[mi] = a_base + (uint32_t)(row * LDAE + (lg >> 1) * 8) * 2u;
    }
    uint32_t b_row[2];
#pragma unroll
    for (int nj = 0; nj < 2; ++nj) {
        int n = wn * 32 + (nj * 2 + (lg >> 1)) * 8 + lr;
        b_row[nj] = b_base + (uint32_t)(n * LDBF + (lg & 1) * 8) * 2u;
    }

    for (int op = 0; op < NO; ++op) {
        asm volatile("cp.async.wait_group 0;");
        __syncthreads();

        float acc[3][4][4];
#pragma unroll
        for (int mi = 0; mi < 3; ++mi)
#pragma unroll
            for (int ni = 0; ni < 4; ++ni)
#pragma unroll
                for (int q = 0; q < 4; ++q) acc[mi][ni][q] = 0.f;

#pragma unroll
        for (int ks = 0; ks < 12; ++ks) {
            const uint32_t koff = (uint32_t)(ks * 16) * 2u;
            uint32_t fa[3][4], fb[4][2];
#pragma unroll
            for (int mi = 0; mi < 3; ++mi)
                LDSM_X4(fa[mi][0], fa[mi][1], fa[mi][2], fa[mi][3],
                        a_row[mi] + koff);
#pragma unroll
            for (int nj = 0; nj < 2; ++nj)
                LDSM_X4(fb[2 * nj][0], fb[2 * nj][1], fb[2 * nj + 1][0], fb[2 * nj + 1][1],
                        b_row[nj] + koff);
#pragma unroll
            for (int mi = 0; mi < 3; ++mi)
#pragma unroll
                for (int ni = 0; ni < 4; ++ni)
                    MMA_F16(acc[mi][ni], fa[mi], fb[ni]);
        }

        __syncthreads();

        if (op + 1 < NO) {
            const __half* Wn = Wp + (long long)(op + 1) * 192 * CDIM;
#pragma unroll
            for (int c = 0; c < 18; ++c) {
                int ch = c * 256 + tid;
                int row = ch / 24, col = ch % 24;
                uint32_t doff = (uint32_t)(row * LDAE + col * 8) * 2u;
                cp_async16(a_base + doff, Wn + (long long)row * CDIM + col * 8);
            }
            asm volatile("cp.async.commit_group;");
        }

        const int ob = op * 192;
#pragma unroll
        for (int mi = 0; mi < 3; ++mi) {
            int r = ob + wm * 48 + mi * 16 + (lane >> 2);
#pragma unroll
            for (int ni = 0; ni < 4; ++ni) {
                int c = n0 + wn * 32 + ni * 8 + (lane & 3) * 2;
                st_out(&Yp[(long long)r * NPIX + c], acc[mi][ni][0], acc[mi][ni][1]);
                st_out(&Yp[(long long)(r + 8) * NPIX + c], acc[mi][ni][2], acc[mi][ni][3]);
            }
        }
    }
}

// ---------------------------------------------------------------------------
// Weight prep (also zeroes gram/norm accumulators when base==0)
// ---------------------------------------------------------------------------
__global__ void prep_wqkv_kernel(const float* __restrict__ W, int base)
{
    int lin = blockIdx.x * blockDim.x + threadIdx.x;
    if (base == 0) {
        if (lin < BATCH * HEADS * CHH * CHH) g_gram[lin] = 0.f;
        if (lin < BATCH * CDIM) { g_nq[lin] = 0.f; g_nk[lin] = 0.f; }
    }
    int idx = base + lin;
    if (idx >= C3 * CDIM) return;
    g_wq[idx] = __float2half(W[idx]);
}

// ---------------------------------------------------------------------------
// 3x3 depthwise conv, padding 1; fp16 in; q/k -> fp32, v -> fp16. 8 px/thread.
// ---------------------------------------------------------------------------
__global__ void dwconv_kernel(const __half* __restrict__ in,
                              const float* __restrict__ wdw,
                              float* __restrict__ outqk,
                              __half* __restrict__ outv)
{
    long long idx = (long long)blockIdx.x * blockDim.x + threadIdx.x;
    if (idx >= (long long)BATCH * C3 * (NPIX / 8)) return;
    const int n8 = (int)(idx & (NPIX / 8 - 1));
    const int t = (int)(idx >> 11);
    const int ch = t % C3;
    const int b = t / C3;
    const int y = n8 >> 4;
    const int x0 = (n8 & 15) * 8;
    const float* w = wdw + ch * 9;
    const __half* p = in + ((long long)b * C3 + ch) * NPIX;

    float o[8];
#pragma unroll
    for (int i = 0; i < 8; ++i) o[i] = 0.f;
#pragma unroll
    for (int r = 0; r < 3; ++r) {
        int yy = y + r - 1;
        if (yy < 0 || yy > IMW - 1) continue;
        const __half* row = p + yy * IMW;
        uint4 cc = *reinterpret_cast<const uint4*>(&row[x0]);
        float2 p0 = __half22float2(*reinterpret_cast<const __half2*>(&cc.x));
        float2 p1 = __half22float2(*reinterpret_cast<const __half2*>(&cc.y));
        float2 p2 = __half22float2(*reinterpret_cast<const __half2*>(&cc.z));
        float2 p3 = __half22float2(*reinterpret_cast<const __half2*>(&cc.w));
        float e[10];
        e[0] = (x0 > 0) ? __half2float(row[x0 - 1]) : 0.f;
        e[1] = p0.x; e[2] = p0.y; e[3] = p1.x; e[4] = p1.y;
        e[5] = p2.x; e[6] = p2.y; e[7] = p3.x; e[8] = p3.y;
        e[9] = (x0 < IMW - 8) ? __half2float(row[x0 + 8]) : 0.f;
        float w0 = w[r * 3], w1 = w[r * 3 + 1], w2 = w[r * 3 + 2];
#pragma unroll
        for (int i = 0; i < 8; ++i)
            o[i] += w0 * e[i] + w1 * e[i + 1] + w2 * e[i + 2];
    }

    if (ch < 2 * CDIM) {
        float* op = outqk + ((long long)b * 2 * CDIM + ch) * NPIX + y * IMW + x0;
        *reinterpret_cast<float4*>(op) = make_float4(o[0], o[1], o[2], o[3]);
        *reinterpret_cast<float4*>(op + 4) = make_float4(o[4], o[5], o[6], o[7]);
    } else {
        __half* op = outv + ((long long)b * CDIM + (ch - 2 * CDIM)) * NPIX + y * IMW + x0;
        uint4 res;
        res.x = pack_h2(__float2half(o[0]), __float2half(o[1]));
        res.y = pack_h2(__float2half(o[2]), __float2half(o[3]));
        res.z = pack_h2(__float2half(o[4]), __float2half(o[5]));
        res.w = pack_h2(__float2half(o[6]), __float2half(o[7]));
        *reinterpret_cast<uint4*>(op) = res;
    }
}

// ---------------------------------------------------------------------------
// Gram + fused norms (reads fp32 q/k from g_qkv2)
// ---------------------------------------------------------------------------
__global__ void gram_kernel(const float* __restrict__ feat)
{
    __shared__ float QF[4][CHH][64];
    __shared__ float KF[4][CHH][64];

    const int bh = blockIdx.y;
    const int b = bh >> 3, hd = bh & 7;
    const int n0 = blockIdx.x * 1024;
    const int t = threadIdx.x;
    const int g = t >> 6, l = t & 63;
    const int li = l >> 3, lj = l & 7;
    const int i0 = li * 3, j0 = lj * 3;

    const float* qbase = g_qkv2 + ((long long)b * 2 * CDIM + hd * CHH) * NPIX;
    const float* kbase = g_qkv2 + ((long long)b * 2 * CDIM + CDIM + hd * CHH) * NPIX;
    const float* fbase = feat + ((long long)b * CDIM + hd * CHH) * NPIX;

    float acc[3][3];
#pragma unroll
    for (int a = 0; a < 3; ++a)
#pragma unroll
        for (int cc = 0; cc < 3; ++cc) acc[a][cc] = 0.f;
    float nqp = 0.f, nkp = 0.f;

    for (int s = 0; s < 1024; s += 256) {
        const int nb = n0 + s + g * 64;
        for (int e = l; e < CHH * 64; e += 64) {
            int i = e >> 6, nn = e & 63;
            long long off = (long long)i * NPIX + nb + nn;
            float fv = fbase[off];
            QF[g][i][nn] = qbase[off] * fv;
            KF[g][i][nn] = kbase[off] * fv;
        }
        __syncthreads();
#pragma unroll 4
        for (int it = 0; it < 64; ++it) {
            int nn = (it + l) & 63;
            float q0 = QF[g][i0 + 0][nn];
            float q1 = QF[g][i0 + 1][nn];
            float q2 = QF[g][i0 + 2][nn];
            float k0 = KF[g][j0 + 0][nn];
            float k1 = KF[g][j0 + 1][nn];
            float k2 = KF[g][j0 + 2][nn];
            acc[0][0] += q0 * k0; acc[0][1] += q0 * k1; acc[0][2] += q0 * k2;
            acc[1][0] += q1 * k0; acc[1][1] += q1 * k1; acc[1][2] += q1 * k2;
            acc[2][0] += q2 * k0; acc[2][1] += q2 * k1; acc[2][2] += q2 * k2;
        }
        if (l < CHH) {
#pragma unroll 4
            for (int it = 0; it < 64; ++it) {
                int nn = (it + l) & 63;
                float qv = QF[g][l][nn]; nqp += qv * qv;
                float kv = KF[g][l][nn]; nkp += kv * kv;
            }
        }
        __syncthreads();
    }

#pragma unroll
    for (int a = 0; a < 3; ++a)
#pragma unroll
        for (int cc = 0; cc < 3; ++cc)
            atomicAdd(&g_gram[(bh * CHH + i0 + a) * CHH + j0 + cc], acc[a][cc]);
    if (l < CHH) {
        atomicAdd(&g_nq[b * CDIM + hd * CHH + l], nqp);
        atomicAdd(&g_nk[b * CDIM + hd * CHH + l], nkp);
    }
}

// ---------------------------------------------------------------------------
// Softmax + W_eff = W_proj @ A_blockdiag, emitted fp16 [192][192]
// ---------------------------------------------------------------------------
__global__ void softmax_weff_kernel(const float* __restrict__ temp,
                                    const float* __restrict__ Wp)
{
    const int b = blockIdx.x;
    const int t = threadIdx.x;            // 384
    __shared__ float A[HEADS][CHH][CHH];
    __shared__ float qinv[CDIM], kinv[CDIM];

    if (t < CDIM) {
        qinv[t] = 1.0f / fmaxf(sqrtf(g_nq[b * CDIM + t]), 1e-12f);
    } else if (t < 2 * CDIM) {
        int c = t - CDIM;
        kinv[c] = 1.0f / fmaxf(sqrtf(g_nk[b * CDIM + c]), 1e-12f);
    }
    __syncthreads();

    if (t < CDIM) {
        const int hd = t / CHH, i = t % CHH;
        const float tp = temp[hd];
        const float qi = qinv[hd * CHH + i];
        float row[CHH];
        float m = -1e30f;
#pragma unroll
        for (int j = 0; j < CHH; ++j) {
            float v = g_gram[((b * HEADS + hd) * CHH + i) * CHH + j]
                      * tp * qi * kinv[hd * CHH + j];
            row[j] = v;
            m = fmaxf(m, v);
        }
        float ssum = 0.f;
#pragma unroll
        for (int j = 0; j < CHH; ++j) { row[j] = expf(row[j] - m); ssum += row[j]; }
        float inv = 1.0f / ssum;
#pragma unroll
        for (int j = 0; j < CHH; ++j) A[hd][i][j] = row[j] * inv;
    }
    __syncthreads();

    for (int idx = t; idx < CDIM * CDIM; idx += 384) {
        const int o = idx / CDIM, cc = idx % CDIM;
        const int hd = cc / CHH, j = cc % CHH;
        float s = 0.f;
#pragma unroll
        for (int i = 0; i < CHH; ++i)
            s += Wp[o * CDIM + hd * CHH + i] * A[hd][i][j];
        g_weff[(long long)b * CDIM * CDIM + idx] = __float2half(s);
    }
}

// ---------------------------------------------------------------------------
extern "C" void kernel_launch(void* const* d_in, const int* in_sizes, int n_in,
                              void* d_out, int out_size)
{
    (void)in_sizes; (void)n_in; (void)out_size;
    const float* x     = (const float*)d_in[0];
    const float* feat  = (const float*)d_in[1];
    const float* Wqkv  = (const float*)d_in[2];
    const float* Wdw   = (const float*)d_in[3];
    const float* Wproj = (const float*)d_in[4];
    const float* temp  = (const float*)d_in[5];
    float* out = (float*)d_out;

    float *qkv2;
    __half *qkv1, *vh, *wq, *wf;
    cudaGetSymbolAddress((void**)&qkv1, g_qkv1);
    cudaGetSymbolAddress((void**)&qkv2, g_qkv2);
    cudaGetSymbolAddress((void**)&vh, g_vh);
    cudaGetSymbolAddress((void**)&wq, g_wq);
    cudaGetSymbolAddress((void**)&wf, g_weff);

    static int smem_set = 0;
    if (!smem_set) {
        cudaFuncSetAttribute(gemm_mma<float, __half>,
                             cudaFuncAttributeMaxDynamicSharedMemorySize, SMEM_GEMM);
        cudaFuncSetAttribute(gemm_mma<__half, float>,
                             cudaFuncAttributeMaxDynamicSharedMemorySize, SMEM_GEMM);
        smem_set = 1;
    }

    const int HALF_W = C3 * CDIM / 2;

    // 1,2) weight prep (+ accumulator zeroing)
    prep_wqkv_kernel<<<(HALF_W + 255) / 256, 256>>>(Wqkv, 0);
    prep_wqkv_kernel<<<(HALF_W + 255) / 256, 256>>>(Wqkv, HALF_W);

    // 3) qkv1 = W_qkv @ x  (fp32 B in, fp16 out; B-stationary, 3 o-panels)
    gemm_mma<float, __half><<<dim3(NPIX / 64, BATCH), 256, SMEM_GEMM>>>(
        wq, 0LL, x, (long long)CDIM * NPIX, qkv1, (long long)C3 * NPIX, 3);

    // 4) depthwise conv (fp16 in; q/k fp32, v fp16)   [ncu slot 4]
    {
        long long total = (long long)BATCH * C3 * (NPIX / 8);
        dwconv_kernel<<<(int)((total + 255) / 256), 256>>>(qkv1, Wdw, qkv2, vh);
    }

    // 5) Gram + norms
    gram_kernel<<<dim3(16, BATCH * HEADS), 256>>>(feat);

    // 6) softmax + W_eff (fp16)
    softmax_weff_kernel<<<BATCH, 384>>>(temp, Wproj);

    // 7) out = W_eff @ v  (fp16 B in, fp32 out)
    gemm_mma<__half, float><<<dim3(NPIX / 64, BATCH), 256, SMEM_GEMM>>>(
        wf, (long long)CDIM * CDIM, vh, (long long)CDIM * NPIX,
        out, (long long)CDIM * NPIX, 1);
}